// round 2
// baseline (speedup 1.0000x reference)
#include <cuda_runtime.h>
#include <math.h>

// Problem constants
#define B_    2
#define S_    2048
#define H_    2048
#define NH    32
#define NKV   8
#define HD    64
#define KVD   512           // NKV * HD
#define MROWS 4096          // B_ * S_

// Scratch (allocation-free rule: __device__ globals)
__device__ float g_q [MROWS * H_];    // 32 MB
__device__ float g_k [MROWS * KVD];   //  8 MB
__device__ float g_v [MROWS * KVD];   //  8 MB
__device__ float g_ao[MROWS * H_];    // 32 MB

// ---------------------------------------------------------------------------
// C[M,N] = A[M,K] @ B[N,K]^T   (both A and B are K-major; matches einsum bsh,oh->bso)
// 128x128 block tile, BK=16, 256 threads, 8x8 register tile per thread.
// ---------------------------------------------------------------------------
__global__ void __launch_bounds__(256)
sgemm_abt(const float* __restrict__ A, const float* __restrict__ B,
          float* __restrict__ C, int M, int N, int K) {
    __shared__ float As[16][128];
    __shared__ float Bs[16][132];

    const int t  = threadIdx.x;
    const int m0 = blockIdx.y * 128;
    const int n0 = blockIdx.x * 128;
    const int tx = t & 15;
    const int ty = t >> 4;
    const int lr = t >> 2;          // 0..63
    const int lc = (t & 3) * 4;     // 0,4,8,12

    float acc[8][8];
#pragma unroll
    for (int i = 0; i < 8; i++)
#pragma unroll
        for (int j = 0; j < 8; j++) acc[i][j] = 0.f;

    for (int k0 = 0; k0 < K; k0 += 16) {
#pragma unroll
        for (int h = 0; h < 2; h++) {
            int row = lr + h * 64;
            float4 av = *(const float4*)(A + (size_t)(m0 + row) * K + k0 + lc);
            As[lc + 0][row] = av.x; As[lc + 1][row] = av.y;
            As[lc + 2][row] = av.z; As[lc + 3][row] = av.w;
            float4 bv = *(const float4*)(B + (size_t)(n0 + row) * K + k0 + lc);
            Bs[lc + 0][row] = bv.x; Bs[lc + 1][row] = bv.y;
            Bs[lc + 2][row] = bv.z; Bs[lc + 3][row] = bv.w;
        }
        __syncthreads();
#pragma unroll
        for (int k = 0; k < 16; k++) {
            float ra[8], rb[8];
            float4 a0 = *(const float4*)&As[k][ty * 8];
            float4 a1 = *(const float4*)&As[k][ty * 8 + 4];
            ra[0]=a0.x; ra[1]=a0.y; ra[2]=a0.z; ra[3]=a0.w;
            ra[4]=a1.x; ra[5]=a1.y; ra[6]=a1.z; ra[7]=a1.w;
            float4 b0 = *(const float4*)&Bs[k][tx * 8];
            float4 b1 = *(const float4*)&Bs[k][tx * 8 + 4];
            rb[0]=b0.x; rb[1]=b0.y; rb[2]=b0.z; rb[3]=b0.w;
            rb[4]=b1.x; rb[5]=b1.y; rb[6]=b1.z; rb[7]=b1.w;
#pragma unroll
            for (int i = 0; i < 8; i++)
#pragma unroll
                for (int j = 0; j < 8; j++)
                    acc[i][j] = fmaf(ra[i], rb[j], acc[i][j]);
        }
        __syncthreads();
    }
#pragma unroll
    for (int i = 0; i < 8; i++) {
        float* cp = C + (size_t)(m0 + ty * 8 + i) * N + n0 + tx * 8;
#pragma unroll
        for (int j = 0; j < 8; j += 4) {
            float4 v = make_float4(acc[i][j], acc[i][j+1], acc[i][j+2], acc[i][j+3]);
            *(float4*)(cp + j) = v;
        }
    }
}

// ---------------------------------------------------------------------------
// RoPE in place on Q[4096,2048] and K[4096,512]. One thread per rotation pair.
// ---------------------------------------------------------------------------
__global__ void rope_kernel(float* __restrict__ q, float* __restrict__ k,
                            int total_q, int total) {
    int idx = blockIdx.x * blockDim.x + threadIdx.x;
    if (idx >= total) return;
    float* ptr;
    int row, p;
    if (idx < total_q) {                 // Q: 32 heads * 32 pairs = 1024 per row
        row = idx >> 10;
        int rem = idx & 1023;
        ptr = q + (size_t)row * H_ + (rem >> 5) * HD;
        p = rem & 31;
    } else {                             // K: 8 heads * 32 pairs = 256 per row
        int i2 = idx - total_q;
        row = i2 >> 8;
        int rem = i2 & 255;
        ptr = k + (size_t)row * KVD + (rem >> 5) * HD;
        p = rem & 31;
    }
    int pos = row & (S_ - 1);
    double inv = exp(-((double)(2 * p) / 64.0) * log(10000.0));
    double ang = (double)pos * inv;
    float c = (float)cos(ang), s = (float)sin(ang);
    float x0 = ptr[p], x1 = ptr[p + 32];
    ptr[p]      = x0 * c - x1 * s;
    ptr[p + 32] = x1 * c + x0 * s;
}

// ---------------------------------------------------------------------------
// Causal flash attention, GQA (4 Q heads per KV head).
// Block = 128 threads = 128 query rows; K/V tiles of 32 rows in SMEM.
// Every inner-loop SMEM read is a warp broadcast -> FMA-bound.
// ---------------------------------------------------------------------------
__global__ void __launch_bounds__(128)
flash_kernel(const float* __restrict__ Q, const float* __restrict__ K,
             const float* __restrict__ V, float* __restrict__ O) {
    __shared__ float Ks[32][68];
    __shared__ float Vs[32][68];

    const int t   = threadIdx.x;
    const int qb  = blockIdx.x;
    const int h   = blockIdx.y;
    const int b   = blockIdx.z;
    const int kvh = h >> 2;
    const int qrow = qb * 128 + t;
    const float* qptr = Q + ((size_t)(b * S_) + qrow) * H_ + h * HD;

    float o[64];
#pragma unroll
    for (int d = 0; d < 64; d++) o[d] = 0.f;
    float m = -3.0e38f, l = 0.f;
    const float scale = 0.125f;           // 1/sqrt(64)
    const int kend = qb * 128 + 128;

    for (int k0 = 0; k0 < kend; k0 += 32) {
        const float* kb = K + ((size_t)(b * S_) + k0) * KVD + kvh * HD;
        const float* vb = V + ((size_t)(b * S_) + k0) * KVD + kvh * HD;
#pragma unroll
        for (int it = 0; it < 4; it++) {
            int i = t + it * 128;               // 0..511
            int r = i >> 4;
            int c = (i & 15) << 2;
            *(float4*)&Ks[r][c] = *(const float4*)(kb + (size_t)r * KVD + c);
            *(float4*)&Vs[r][c] = *(const float4*)(vb + (size_t)r * KVD + c);
        }
        __syncthreads();

        float s[32];
#pragma unroll
        for (int j = 0; j < 32; j++) s[j] = 0.f;

#pragma unroll 1
        for (int d4 = 0; d4 < 16; d4++) {
            float4 qv = *(const float4*)(qptr + d4 * 4);
#pragma unroll
            for (int j = 0; j < 32; j++) {
                float4 kv = *(const float4*)&Ks[j][d4 * 4];
                s[j] += qv.x * kv.x + qv.y * kv.y + qv.z * kv.z + qv.w * kv.w;
            }
        }

        float mx = m;
#pragma unroll
        for (int j = 0; j < 32; j++) {
            s[j] = (k0 + j > qrow) ? -1.0e9f : s[j] * scale;
            mx = fmaxf(mx, s[j]);
        }
        float corr = __expf(m - mx);
        l *= corr;
#pragma unroll
        for (int d = 0; d < 64; d++) o[d] *= corr;
#pragma unroll
        for (int j = 0; j < 32; j++) {
            float p = __expf(s[j] - mx);
            l += p;
            s[j] = p;
        }
        m = mx;

#pragma unroll
        for (int j = 0; j < 32; j++) {
            float p = s[j];
#pragma unroll
            for (int d4 = 0; d4 < 16; d4++) {
                float4 vv = *(const float4*)&Vs[j][d4 * 4];
                o[d4 * 4 + 0] += p * vv.x;
                o[d4 * 4 + 1] += p * vv.y;
                o[d4 * 4 + 2] += p * vv.z;
                o[d4 * 4 + 3] += p * vv.w;
            }
        }
        __syncthreads();
    }

    float invl = 1.f / l;
    float* op = O + ((size_t)(b * S_) + qrow) * H_ + h * HD;
#pragma unroll
    for (int d4 = 0; d4 < 16; d4++) {
        float4 v = make_float4(o[d4*4] * invl, o[d4*4+1] * invl,
                               o[d4*4+2] * invl, o[d4*4+3] * invl);
        *(float4*)(op + d4 * 4) = v;
    }
}

// ---------------------------------------------------------------------------
// inputs (metadata order): x, position_ids(int64, unused: pos = s), mask(unused:
// causal -1e9 reproduced exactly), wq, wk, wv, wo. output: float32 [2,2048,2048]
// ---------------------------------------------------------------------------
extern "C" void kernel_launch(void* const* d_in, const int* in_sizes, int n_in,
                              void* d_out, int out_size) {
    const float* x  = (const float*)d_in[0];
    const float* wq = (const float*)d_in[3];
    const float* wk = (const float*)d_in[4];
    const float* wv = (const float*)d_in[5];
    const float* wo = (const float*)d_in[6];
    float* out = (float*)d_out;

    float *q, *k, *v, *ao;
    cudaGetSymbolAddress((void**)&q,  g_q);
    cudaGetSymbolAddress((void**)&k,  g_k);
    cudaGetSymbolAddress((void**)&v,  g_v);
    cudaGetSymbolAddress((void**)&ao, g_ao);

    // Projections: Q/K/V
    dim3 gq(H_ / 128, MROWS / 128);        // 16 x 32
    dim3 gkv(KVD / 128, MROWS / 128);      // 4 x 32
    sgemm_abt<<<gq, 256>>>(x, wq, q, MROWS, H_, H_);
    sgemm_abt<<<gkv, 256>>>(x, wk, k, MROWS, KVD, H_);
    sgemm_abt<<<gkv, 256>>>(x, wv, v, MROWS, KVD, H_);

    // RoPE on Q and K
    int total_q = MROWS * NH * (HD / 2);   // 4,194,304
    int total   = total_q + MROWS * NKV * (HD / 2);
    rope_kernel<<<(total + 255) / 256, 256>>>(q, k, total_q, total);

    // Causal GQA flash attention
    dim3 ga(S_ / 128, NH, B_);             // 16 x 32 x 2
    flash_kernel<<<ga, 128>>>(q, k, v, ao);

    // Output projection
    sgemm_abt<<<gq, 256>>>(ao, wo, out, MROWS, H_, H_);
}

// round 3
// speedup vs baseline: 1.5308x; 1.5308x over previous
#include <cuda_runtime.h>
#include <cuda_bf16.h>
#include <math.h>
#include <stdint.h>

// Problem constants
#define B_    2
#define S_    2048
#define H_    2048
#define NH    32
#define NKV   8
#define HD    64
#define KVD   512           // NKV * HD
#define MROWS 4096          // B_ * S_

// Scratch (allocation-free rule: __device__ globals)
__device__ float g_q [MROWS * H_];    // 32 MB
__device__ float g_k [MROWS * KVD];   //  8 MB
__device__ float g_v [MROWS * KVD];   //  8 MB
__device__ float g_ao[MROWS * H_];    // 32 MB
__device__ float2 g_cs[S_ * 32];      // cos/sin table, 512 KB

// ---------------------------------------------------------------------------
// mma.sync bf16 helpers
// ---------------------------------------------------------------------------
__device__ __forceinline__ void mma16816(float* c, const uint32_t* a, const uint32_t* b) {
    asm volatile(
        "mma.sync.aligned.m16n8k16.row.col.f32.bf16.bf16.f32 "
        "{%0,%1,%2,%3}, {%4,%5,%6,%7}, {%8,%9}, {%0,%1,%2,%3};\n"
        : "+f"(c[0]), "+f"(c[1]), "+f"(c[2]), "+f"(c[3])
        : "r"(a[0]), "r"(a[1]), "r"(a[2]), "r"(a[3]), "r"(b[0]), "r"(b[1]));
}
__device__ __forceinline__ void ldsm4(uint32_t* r, uint32_t addr) {
    asm volatile("ldmatrix.sync.aligned.m8n8.x4.shared.b16 {%0,%1,%2,%3}, [%4];\n"
                 : "=r"(r[0]), "=r"(r[1]), "=r"(r[2]), "=r"(r[3]) : "r"(addr));
}

// ---------------------------------------------------------------------------
// C[M,N] = A[M,K] @ B[N,K]^T  via bf16x3 split (A1B1 + A1B2 + A2B1).
// 128x128 tile, BK=32, 256 threads (8 warps, 2x4), warp tile 64x32.
// ---------------------------------------------------------------------------
#define ST 40   // smem row stride in bf16 elems (conflict-free for ldmatrix)

__global__ void __launch_bounds__(256)
gemm_bf16x3(const float* __restrict__ A, const float* __restrict__ B,
            float* __restrict__ C, int M, int N, int K) {
    __shared__ __nv_bfloat16 Ah[128 * ST];
    __shared__ __nv_bfloat16 Al[128 * ST];
    __shared__ __nv_bfloat16 Bh[128 * ST];
    __shared__ __nv_bfloat16 Bl[128 * ST];

    const int t    = threadIdx.x;
    const int lane = t & 31;
    const int w    = t >> 5;
    const int wm   = (w & 1) * 64;
    const int wn   = (w >> 1) * 32;
    const int m0   = blockIdx.y * 128;
    const int n0   = blockIdx.x * 128;

    // ldmatrix lane address decomposition
    const int g = lane >> 3, r = lane & 7;
    const int a_moff = (g & 1) * 8 + r;
    const int a_koff = (g >> 1) * 8;
    const int b_noff = (g >> 1) * 8 + r;
    const int b_koff = (g & 1) * 8;

    const uint32_t sAh = (uint32_t)__cvta_generic_to_shared(Ah);
    const uint32_t sAl = (uint32_t)__cvta_generic_to_shared(Al);
    const uint32_t sBh = (uint32_t)__cvta_generic_to_shared(Bh);
    const uint32_t sBl = (uint32_t)__cvta_generic_to_shared(Bl);

    float acc[4][4][4];
#pragma unroll
    for (int i = 0; i < 4; i++)
#pragma unroll
        for (int j = 0; j < 4; j++)
#pragma unroll
            for (int e = 0; e < 4; e++) acc[i][j][e] = 0.f;

    for (int k0 = 0; k0 < K; k0 += 32) {
        // load fp32 tiles, split into hi/lo bf16, store to smem
#pragma unroll
        for (int i = 0; i < 4; i++) {
            int idx = t + i * 256;           // 0..1023 (128 rows x 8 float4)
            int row = idx >> 3;
            int c4  = (idx & 7) << 2;
            float4 av = *(const float4*)(A + (size_t)(m0 + row) * K + k0 + c4);
            float4 bv = *(const float4*)(B + (size_t)(n0 + row) * K + k0 + c4);
            __nv_bfloat16 h0 = __float2bfloat16(av.x), h1 = __float2bfloat16(av.y);
            __nv_bfloat16 h2 = __float2bfloat16(av.z), h3 = __float2bfloat16(av.w);
            __nv_bfloat16 l0 = __float2bfloat16(av.x - __bfloat162float(h0));
            __nv_bfloat16 l1 = __float2bfloat16(av.y - __bfloat162float(h1));
            __nv_bfloat16 l2 = __float2bfloat16(av.z - __bfloat162float(h2));
            __nv_bfloat16 l3 = __float2bfloat16(av.w - __bfloat162float(h3));
            int o = row * ST + c4;
            *(__nv_bfloat162*)&Ah[o]     = __nv_bfloat162(h0, h1);
            *(__nv_bfloat162*)&Ah[o + 2] = __nv_bfloat162(h2, h3);
            *(__nv_bfloat162*)&Al[o]     = __nv_bfloat162(l0, l1);
            *(__nv_bfloat162*)&Al[o + 2] = __nv_bfloat162(l2, l3);
            h0 = __float2bfloat16(bv.x); h1 = __float2bfloat16(bv.y);
            h2 = __float2bfloat16(bv.z); h3 = __float2bfloat16(bv.w);
            l0 = __float2bfloat16(bv.x - __bfloat162float(h0));
            l1 = __float2bfloat16(bv.y - __bfloat162float(h1));
            l2 = __float2bfloat16(bv.z - __bfloat162float(h2));
            l3 = __float2bfloat16(bv.w - __bfloat162float(h3));
            *(__nv_bfloat162*)&Bh[o]     = __nv_bfloat162(h0, h1);
            *(__nv_bfloat162*)&Bh[o + 2] = __nv_bfloat162(h2, h3);
            *(__nv_bfloat162*)&Bl[o]     = __nv_bfloat162(l0, l1);
            *(__nv_bfloat162*)&Bl[o + 2] = __nv_bfloat162(l2, l3);
        }
        __syncthreads();

#pragma unroll
        for (int ks = 0; ks < 2; ks++) {
            const int kk = ks * 16;
            uint32_t af[4][4], b1[2][4], b2[2][4];
#pragma unroll
            for (int mi = 0; mi < 4; mi++)
                ldsm4(af[mi], sAh + 2u * ((wm + mi * 16 + a_moff) * ST + kk + a_koff));
#pragma unroll
            for (int nb = 0; nb < 2; nb++) {
                ldsm4(b1[nb], sBh + 2u * ((wn + nb * 16 + b_noff) * ST + kk + b_koff));
                ldsm4(b2[nb], sBl + 2u * ((wn + nb * 16 + b_noff) * ST + kk + b_koff));
            }
            // A1*B1 + A1*B2
#pragma unroll
            for (int mi = 0; mi < 4; mi++)
#pragma unroll
                for (int ni = 0; ni < 4; ni++) {
                    mma16816(acc[mi][ni], af[mi], &b1[ni >> 1][(ni & 1) * 2]);
                    mma16816(acc[mi][ni], af[mi], &b2[ni >> 1][(ni & 1) * 2]);
                }
            // A2*B1
#pragma unroll
            for (int mi = 0; mi < 4; mi++)
                ldsm4(af[mi], sAl + 2u * ((wm + mi * 16 + a_moff) * ST + kk + a_koff));
#pragma unroll
            for (int mi = 0; mi < 4; mi++)
#pragma unroll
                for (int ni = 0; ni < 4; ni++)
                    mma16816(acc[mi][ni], af[mi], &b1[ni >> 1][(ni & 1) * 2]);
        }
        __syncthreads();
    }

    // epilogue
#pragma unroll
    for (int mi = 0; mi < 4; mi++) {
        int row = m0 + wm + mi * 16 + (lane >> 2);
#pragma unroll
        for (int ni = 0; ni < 4; ni++) {
            int col = n0 + wn + ni * 8 + (lane & 3) * 2;
            *(float2*)&C[(size_t)row * N + col]       = make_float2(acc[mi][ni][0], acc[mi][ni][1]);
            *(float2*)&C[(size_t)(row + 8) * N + col] = make_float2(acc[mi][ni][2], acc[mi][ni][3]);
        }
    }
}

// ---------------------------------------------------------------------------
// RoPE cos/sin table (fp64 internally for exact match to reference), then
// memory-bound apply pass.
// ---------------------------------------------------------------------------
__global__ void cs_table_kernel() {
    int i = blockIdx.x * blockDim.x + threadIdx.x;   // 65536
    if (i >= S_ * 32) return;
    int pos = i >> 5, p = i & 31;
    double inv = exp(-((double)(2 * p) / 64.0) * log(10000.0));
    double ang = (double)pos * inv;
    g_cs[i] = make_float2((float)cos(ang), (float)sin(ang));
}

__global__ void rope_kernel(float* __restrict__ q, float* __restrict__ k,
                            int total_q, int total) {
    int idx = blockIdx.x * blockDim.x + threadIdx.x;
    if (idx >= total) return;
    float* ptr;
    int row, p;
    if (idx < total_q) {                 // Q: 32 heads * 32 pairs = 1024 per row
        row = idx >> 10;
        int rem = idx & 1023;
        ptr = q + (size_t)row * H_ + (rem >> 5) * HD;
        p = rem & 31;
    } else {                             // K: 8 heads * 32 pairs = 256 per row
        int i2 = idx - total_q;
        row = i2 >> 8;
        int rem = i2 & 255;
        ptr = k + (size_t)row * KVD + (rem >> 5) * HD;
        p = rem & 31;
    }
    int pos = row & (S_ - 1);
    float2 cs = g_cs[pos * 32 + p];
    float x0 = ptr[p], x1 = ptr[p + 32];
    ptr[p]      = x0 * cs.x - x1 * cs.y;
    ptr[p + 32] = x1 * cs.x + x0 * cs.y;
}

// ---------------------------------------------------------------------------
// Causal flash attention, GQA (4 Q heads per KV head). Unchanged from R1.
// ---------------------------------------------------------------------------
__global__ void __launch_bounds__(128)
flash_kernel(const float* __restrict__ Q, const float* __restrict__ K,
             const float* __restrict__ V, float* __restrict__ O) {
    __shared__ float Ks[32][68];
    __shared__ float Vs[32][68];

    const int t   = threadIdx.x;
    const int qb  = blockIdx.x;
    const int h   = blockIdx.y;
    const int b   = blockIdx.z;
    const int kvh = h >> 2;
    const int qrow = qb * 128 + t;
    const float* qptr = Q + ((size_t)(b * S_) + qrow) * H_ + h * HD;

    float o[64];
#pragma unroll
    for (int d = 0; d < 64; d++) o[d] = 0.f;
    float m = -3.0e38f, l = 0.f;
    const float scale = 0.125f;           // 1/sqrt(64)
    const int kend = qb * 128 + 128;

    for (int k0 = 0; k0 < kend; k0 += 32) {
        const float* kb = K + ((size_t)(b * S_) + k0) * KVD + kvh * HD;
        const float* vb = V + ((size_t)(b * S_) + k0) * KVD + kvh * HD;
#pragma unroll
        for (int it = 0; it < 4; it++) {
            int i = t + it * 128;               // 0..511
            int rr = i >> 4;
            int c = (i & 15) << 2;
            *(float4*)&Ks[rr][c] = *(const float4*)(kb + (size_t)rr * KVD + c);
            *(float4*)&Vs[rr][c] = *(const float4*)(vb + (size_t)rr * KVD + c);
        }
        __syncthreads();

        float s[32];
#pragma unroll
        for (int j = 0; j < 32; j++) s[j] = 0.f;

#pragma unroll 1
        for (int d4 = 0; d4 < 16; d4++) {
            float4 qv = *(const float4*)(qptr + d4 * 4);
#pragma unroll
            for (int j = 0; j < 32; j++) {
                float4 kv = *(const float4*)&Ks[j][d4 * 4];
                s[j] += qv.x * kv.x + qv.y * kv.y + qv.z * kv.z + qv.w * kv.w;
            }
        }

        float mx = m;
#pragma unroll
        for (int j = 0; j < 32; j++) {
            s[j] = (k0 + j > qrow) ? -1.0e9f : s[j] * scale;
            mx = fmaxf(mx, s[j]);
        }
        float corr = __expf(m - mx);
        l *= corr;
#pragma unroll
        for (int d = 0; d < 64; d++) o[d] *= corr;
#pragma unroll
        for (int j = 0; j < 32; j++) {
            float p = __expf(s[j] - mx);
            l += p;
            s[j] = p;
        }
        m = mx;

#pragma unroll
        for (int j = 0; j < 32; j++) {
            float p = s[j];
#pragma unroll
            for (int d4 = 0; d4 < 16; d4++) {
                float4 vv = *(const float4*)&Vs[j][d4 * 4];
                o[d4 * 4 + 0] += p * vv.x;
                o[d4 * 4 + 1] += p * vv.y;
                o[d4 * 4 + 2] += p * vv.z;
                o[d4 * 4 + 3] += p * vv.w;
            }
        }
        __syncthreads();
    }

    float invl = 1.f / l;
    float* op = O + ((size_t)(b * S_) + qrow) * H_ + h * HD;
#pragma unroll
    for (int d4 = 0; d4 < 16; d4++) {
        float4 v = make_float4(o[d4*4] * invl, o[d4*4+1] * invl,
                               o[d4*4+2] * invl, o[d4*4+3] * invl);
        *(float4*)(op + d4 * 4) = v;
    }
}

// ---------------------------------------------------------------------------
// inputs (metadata order): x, position_ids(int64, unused: pos = s), mask(unused:
// causal -1e9 reproduced exactly), wq, wk, wv, wo. output: float32 [2,2048,2048]
// ---------------------------------------------------------------------------
extern "C" void kernel_launch(void* const* d_in, const int* in_sizes, int n_in,
                              void* d_out, int out_size) {
    const float* x  = (const float*)d_in[0];
    const float* wq = (const float*)d_in[3];
    const float* wk = (const float*)d_in[4];
    const float* wv = (const float*)d_in[5];
    const float* wo = (const float*)d_in[6];
    float* out = (float*)d_out;

    float *q, *k, *v, *ao;
    cudaGetSymbolAddress((void**)&q,  g_q);
    cudaGetSymbolAddress((void**)&k,  g_k);
    cudaGetSymbolAddress((void**)&v,  g_v);
    cudaGetSymbolAddress((void**)&ao, g_ao);

    // cos/sin table (cheap; runs every launch for determinism)
    cs_table_kernel<<<(S_ * 32 + 255) / 256, 256>>>();

    // Projections: Q/K/V via bf16x3 tensor-core GEMM
    dim3 gq(H_ / 128, MROWS / 128);        // 16 x 32
    dim3 gkv(KVD / 128, MROWS / 128);      // 4 x 32
    gemm_bf16x3<<<gq, 256>>>(x, wq, q, MROWS, H_, H_);
    gemm_bf16x3<<<gkv, 256>>>(x, wk, k, MROWS, KVD, H_);
    gemm_bf16x3<<<gkv, 256>>>(x, wv, v, MROWS, KVD, H_);

    // RoPE on Q and K
    int total_q = MROWS * NH * (HD / 2);   // 4,194,304
    int total   = total_q + MROWS * NKV * (HD / 2);
    rope_kernel<<<(total + 255) / 256, 256>>>(q, k, total_q, total);

    // Causal GQA flash attention
    dim3 ga(S_ / 128, NH, B_);             // 16 x 32 x 2
    flash_kernel<<<ga, 128>>>(q, k, v, ao);

    // Output projection
    gemm_bf16x3<<<gq, 256>>>(ao, wo, out, MROWS, H_, H_);
}

// round 4
// speedup vs baseline: 3.4412x; 2.2479x over previous
#include <cuda_runtime.h>
#include <cuda_bf16.h>
#include <math.h>
#include <stdint.h>

// Problem constants
#define B_    2
#define S_    2048
#define H_    2048
#define NH    32
#define NKV   8
#define HD    64
#define KVD   512           // NKV * HD
#define MROWS 4096          // B_ * S_

// Scratch (allocation-free rule: __device__ globals)
__device__ float g_q [MROWS * H_];    // 32 MB
__device__ float g_k [MROWS * KVD];   //  8 MB
__device__ float g_v [MROWS * KVD];   //  8 MB
__device__ float g_ao[MROWS * H_];    // 32 MB
__device__ float2 g_cs[S_ * 32];      // cos/sin table

// bf16 hi/lo split copies for tensor-core attention
__device__ __nv_bfloat16 g_qh[MROWS * H_];
__device__ __nv_bfloat16 g_ql[MROWS * H_];
__device__ __nv_bfloat16 g_kh[MROWS * KVD];
__device__ __nv_bfloat16 g_kl[MROWS * KVD];
__device__ __nv_bfloat16 g_vh[MROWS * KVD];
__device__ __nv_bfloat16 g_vl[MROWS * KVD];

// ---------------------------------------------------------------------------
// mma.sync bf16 helpers
// ---------------------------------------------------------------------------
__device__ __forceinline__ void mma16816(float* c, const uint32_t* a, const uint32_t* b) {
    asm volatile(
        "mma.sync.aligned.m16n8k16.row.col.f32.bf16.bf16.f32 "
        "{%0,%1,%2,%3}, {%4,%5,%6,%7}, {%8,%9}, {%0,%1,%2,%3};\n"
        : "+f"(c[0]), "+f"(c[1]), "+f"(c[2]), "+f"(c[3])
        : "r"(a[0]), "r"(a[1]), "r"(a[2]), "r"(a[3]), "r"(b[0]), "r"(b[1]));
}
__device__ __forceinline__ void ldsm4(uint32_t* r, uint32_t addr) {
    asm volatile("ldmatrix.sync.aligned.m8n8.x4.shared.b16 {%0,%1,%2,%3}, [%4];\n"
                 : "=r"(r[0]), "=r"(r[1]), "=r"(r[2]), "=r"(r[3]) : "r"(addr));
}
__device__ __forceinline__ void ldsm4t(uint32_t* r, uint32_t addr) {
    asm volatile("ldmatrix.sync.aligned.m8n8.x4.trans.shared.b16 {%0,%1,%2,%3}, [%4];\n"
                 : "=r"(r[0]), "=r"(r[1]), "=r"(r[2]), "=r"(r[3]) : "r"(addr));
}
__device__ __forceinline__ uint32_t pack_bf16(float a, float b) {
    __nv_bfloat162 t = __floats2bfloat162_rn(a, b);
    return *(uint32_t*)&t;
}

// ---------------------------------------------------------------------------
// C[M,N] = A[M,K] @ B[N,K]^T  via bf16x3 split (A1B1 + A1B2 + A2B1).
// 128x128 tile, BK=32, 256 threads (8 warps, 2x4), warp tile 64x32.
// ---------------------------------------------------------------------------
#define ST 40   // smem row stride in bf16 elems

__global__ void __launch_bounds__(256)
gemm_bf16x3(const float* __restrict__ A, const float* __restrict__ B,
            float* __restrict__ C, int M, int N, int K) {
    __shared__ __nv_bfloat16 Ah[128 * ST];
    __shared__ __nv_bfloat16 Al[128 * ST];
    __shared__ __nv_bfloat16 Bh[128 * ST];
    __shared__ __nv_bfloat16 Bl[128 * ST];

    const int t    = threadIdx.x;
    const int lane = t & 31;
    const int w    = t >> 5;
    const int wm   = (w & 1) * 64;
    const int wn   = (w >> 1) * 32;
    const int m0   = blockIdx.y * 128;
    const int n0   = blockIdx.x * 128;

    const int g = lane >> 3, r = lane & 7;
    const int a_moff = (g & 1) * 8 + r;
    const int a_koff = (g >> 1) * 8;
    const int b_noff = (g >> 1) * 8 + r;
    const int b_koff = (g & 1) * 8;

    const uint32_t sAh = (uint32_t)__cvta_generic_to_shared(Ah);
    const uint32_t sAl = (uint32_t)__cvta_generic_to_shared(Al);
    const uint32_t sBh = (uint32_t)__cvta_generic_to_shared(Bh);
    const uint32_t sBl = (uint32_t)__cvta_generic_to_shared(Bl);

    float acc[4][4][4];
#pragma unroll
    for (int i = 0; i < 4; i++)
#pragma unroll
        for (int j = 0; j < 4; j++)
#pragma unroll
            for (int e = 0; e < 4; e++) acc[i][j][e] = 0.f;

    for (int k0 = 0; k0 < K; k0 += 32) {
#pragma unroll
        for (int i = 0; i < 4; i++) {
            int idx = t + i * 256;
            int row = idx >> 3;
            int c4  = (idx & 7) << 2;
            float4 av = *(const float4*)(A + (size_t)(m0 + row) * K + k0 + c4);
            float4 bv = *(const float4*)(B + (size_t)(n0 + row) * K + k0 + c4);
            __nv_bfloat16 h0 = __float2bfloat16(av.x), h1 = __float2bfloat16(av.y);
            __nv_bfloat16 h2 = __float2bfloat16(av.z), h3 = __float2bfloat16(av.w);
            __nv_bfloat16 l0 = __float2bfloat16(av.x - __bfloat162float(h0));
            __nv_bfloat16 l1 = __float2bfloat16(av.y - __bfloat162float(h1));
            __nv_bfloat16 l2 = __float2bfloat16(av.z - __bfloat162float(h2));
            __nv_bfloat16 l3 = __float2bfloat16(av.w - __bfloat162float(h3));
            int o = row * ST + c4;
            *(__nv_bfloat162*)&Ah[o]     = __nv_bfloat162(h0, h1);
            *(__nv_bfloat162*)&Ah[o + 2] = __nv_bfloat162(h2, h3);
            *(__nv_bfloat162*)&Al[o]     = __nv_bfloat162(l0, l1);
            *(__nv_bfloat162*)&Al[o + 2] = __nv_bfloat162(l2, l3);
            h0 = __float2bfloat16(bv.x); h1 = __float2bfloat16(bv.y);
            h2 = __float2bfloat16(bv.z); h3 = __float2bfloat16(bv.w);
            l0 = __float2bfloat16(bv.x - __bfloat162float(h0));
            l1 = __float2bfloat16(bv.y - __bfloat162float(h1));
            l2 = __float2bfloat16(bv.z - __bfloat162float(h2));
            l3 = __float2bfloat16(bv.w - __bfloat162float(h3));
            *(__nv_bfloat162*)&Bh[o]     = __nv_bfloat162(h0, h1);
            *(__nv_bfloat162*)&Bh[o + 2] = __nv_bfloat162(h2, h3);
            *(__nv_bfloat162*)&Bl[o]     = __nv_bfloat162(l0, l1);
            *(__nv_bfloat162*)&Bl[o + 2] = __nv_bfloat162(l2, l3);
        }
        __syncthreads();

#pragma unroll
        for (int ks = 0; ks < 2; ks++) {
            const int kk = ks * 16;
            uint32_t af[4][4], b1[2][4], b2[2][4];
#pragma unroll
            for (int mi = 0; mi < 4; mi++)
                ldsm4(af[mi], sAh + 2u * ((wm + mi * 16 + a_moff) * ST + kk + a_koff));
#pragma unroll
            for (int nb = 0; nb < 2; nb++) {
                ldsm4(b1[nb], sBh + 2u * ((wn + nb * 16 + b_noff) * ST + kk + b_koff));
                ldsm4(b2[nb], sBl + 2u * ((wn + nb * 16 + b_noff) * ST + kk + b_koff));
            }
#pragma unroll
            for (int mi = 0; mi < 4; mi++)
#pragma unroll
                for (int ni = 0; ni < 4; ni++) {
                    mma16816(acc[mi][ni], af[mi], &b1[ni >> 1][(ni & 1) * 2]);
                    mma16816(acc[mi][ni], af[mi], &b2[ni >> 1][(ni & 1) * 2]);
                }
#pragma unroll
            for (int mi = 0; mi < 4; mi++)
                ldsm4(af[mi], sAl + 2u * ((wm + mi * 16 + a_moff) * ST + kk + a_koff));
#pragma unroll
            for (int mi = 0; mi < 4; mi++)
#pragma unroll
                for (int ni = 0; ni < 4; ni++)
                    mma16816(acc[mi][ni], af[mi], &b1[ni >> 1][(ni & 1) * 2]);
        }
        __syncthreads();
    }

#pragma unroll
    for (int mi = 0; mi < 4; mi++) {
        int row = m0 + wm + mi * 16 + (lane >> 2);
#pragma unroll
        for (int ni = 0; ni < 4; ni++) {
            int col = n0 + wn + ni * 8 + (lane & 3) * 2;
            *(float2*)&C[(size_t)row * N + col]       = make_float2(acc[mi][ni][0], acc[mi][ni][1]);
            *(float2*)&C[(size_t)(row + 8) * N + col] = make_float2(acc[mi][ni][2], acc[mi][ni][3]);
        }
    }
}

// ---------------------------------------------------------------------------
// cos/sin table (fp64 internally, once per launch)
// ---------------------------------------------------------------------------
__global__ void cs_table_kernel() {
    int i = blockIdx.x * blockDim.x + threadIdx.x;
    if (i >= S_ * 32) return;
    int pos = i >> 5, p = i & 31;
    double inv = exp(-((double)(2 * p) / 64.0) * log(10000.0));
    double ang = (double)pos * inv;
    g_cs[i] = make_float2((float)cos(ang), (float)sin(ang));
}

// ---------------------------------------------------------------------------
// Fused RoPE (Q,K) + hi/lo bf16 split of Q, K, V into global arrays.
// ---------------------------------------------------------------------------
__global__ void rope_split_kernel(const float* __restrict__ q,
                                  const float* __restrict__ k,
                                  const float* __restrict__ v) {
    const int NQ = MROWS * 1024;          // q pairs
    const int NK = MROWS * 256;           // k pairs
    const int NV = MROWS * 256;           // v element-pairs
    int idx = blockIdx.x * blockDim.x + threadIdx.x;
    if (idx >= NQ + NK + NV) return;

    if (idx < NQ + NK) {
        const float* src; __nv_bfloat16 *dh, *dl;
        int row, p, head, rowstride;
        if (idx < NQ) {
            row = idx >> 10; int rem = idx & 1023;
            head = rem >> 5; p = rem & 31; rowstride = H_;
            src = q; dh = g_qh; dl = g_ql;
        } else {
            int i2 = idx - NQ;
            row = i2 >> 8; int rem = i2 & 255;
            head = rem >> 5; p = rem & 31; rowstride = KVD;
            src = k; dh = g_kh; dl = g_kl;
        }
        size_t base = (size_t)row * rowstride + head * HD;
        int pos = row & (S_ - 1);
        float2 cs = g_cs[pos * 32 + p];
        float x0 = src[base + p], x1 = src[base + p + 32];
        float y0 = x0 * cs.x - x1 * cs.y;
        float y1 = x1 * cs.x + x0 * cs.y;
        __nv_bfloat16 h0 = __float2bfloat16(y0);
        __nv_bfloat16 h1 = __float2bfloat16(y1);
        dh[base + p]      = h0;
        dh[base + p + 32] = h1;
        dl[base + p]      = __float2bfloat16(y0 - __bfloat162float(h0));
        dl[base + p + 32] = __float2bfloat16(y1 - __bfloat162float(h1));
    } else {
        int i2 = idx - NQ - NK;
        size_t base = (size_t)(i2 >> 8) * KVD + (i2 & 255) * 2;
        float x0 = v[base], x1 = v[base + 1];
        __nv_bfloat16 h0 = __float2bfloat16(x0);
        __nv_bfloat16 h1 = __float2bfloat16(x1);
        g_vh[base]     = h0;
        g_vh[base + 1] = h1;
        g_vl[base]     = __float2bfloat16(x0 - __bfloat162float(h0));
        g_vl[base + 1] = __float2bfloat16(x1 - __bfloat162float(h1));
    }
}

// ---------------------------------------------------------------------------
// Tensor-core causal flash attention (bf16x3 scores, bf16x3 PV).
// Block = 64 q rows, 4 warps (16 rows each). 64-key tiles.
// ---------------------------------------------------------------------------
#define ST2 72

__global__ void __launch_bounds__(128)
flash2(const __nv_bfloat16* __restrict__ Qh, const __nv_bfloat16* __restrict__ Ql,
       const __nv_bfloat16* __restrict__ Kh, const __nv_bfloat16* __restrict__ Kl,
       const __nv_bfloat16* __restrict__ Vh, const __nv_bfloat16* __restrict__ Vl,
       float* __restrict__ O) {
    __shared__ __nv_bfloat16 sKh[64 * ST2], sKl[64 * ST2];
    __shared__ __nv_bfloat16 sVh[64 * ST2], sVl[64 * ST2];

    const int t = threadIdx.x, lane = t & 31, w = t >> 5;
    const int qb = blockIdx.x, h = blockIdx.y, b = blockIdx.z, kvh = h >> 2;
    const int g = lane >> 3, r = lane & 7;
    const int a_row = (g & 1) * 8 + r, a_k = (g >> 1) * 8;
    const int b_row = (g >> 1) * 8 + r, b_k = (g & 1) * 8;

    const uint32_t pKh = (uint32_t)__cvta_generic_to_shared(sKh);
    const uint32_t pKl = (uint32_t)__cvta_generic_to_shared(sKl);
    const uint32_t pVh = (uint32_t)__cvta_generic_to_shared(sVh);
    const uint32_t pVl = (uint32_t)__cvta_generic_to_shared(sVl);

    // ---- stage Q tile through K buffers, pull fragments to registers ----
    const size_t qbase = ((size_t)(b * S_) + qb * 64) * H_ + h * HD;
#pragma unroll
    for (int i = 0; i < 4; i++) {
        int idx = t + i * 128;
        int row = idx >> 3, c = (idx & 7) * 8;
        *(uint4*)&sKh[row * ST2 + c] = *(const uint4*)(Qh + qbase + (size_t)row * H_ + c);
        *(uint4*)&sKl[row * ST2 + c] = *(const uint4*)(Ql + qbase + (size_t)row * H_ + c);
    }
    __syncthreads();
    uint32_t qh[4][4], ql[4][4];
#pragma unroll
    for (int ks = 0; ks < 4; ks++) {
        ldsm4(qh[ks], pKh + 2u * ((w * 16 + a_row) * ST2 + ks * 16 + a_k));
        ldsm4(ql[ks], pKl + 2u * ((w * 16 + a_row) * ST2 + ks * 16 + a_k));
    }
    __syncthreads();

    float o[8][4];
#pragma unroll
    for (int j = 0; j < 8; j++)
#pragma unroll
        for (int e = 0; e < 4; e++) o[j][e] = 0.f;
    float m0 = -3.0e38f, m1 = -3.0e38f, l0 = 0.f, l1 = 0.f;
    const int qr0 = qb * 64 + w * 16 + (lane >> 2);
    const int qr1 = qr0 + 8;
    const int kend = qb * 64 + 64;

    for (int k0 = 0; k0 < kend; k0 += 64) {
        const size_t kb = ((size_t)(b * S_) + k0) * KVD + kvh * HD;
#pragma unroll
        for (int i = 0; i < 4; i++) {
            int idx = t + i * 128;
            int row = idx >> 3, c = (idx & 7) * 8;
            size_t go = kb + (size_t)row * KVD + c;
            int so = row * ST2 + c;
            *(uint4*)&sKh[so] = *(const uint4*)(Kh + go);
            *(uint4*)&sKl[so] = *(const uint4*)(Kl + go);
            *(uint4*)&sVh[so] = *(const uint4*)(Vh + go);
            *(uint4*)&sVl[so] = *(const uint4*)(Vl + go);
        }
        __syncthreads();

        // ---- S = Q K^T (bf16x3) ----
        float s[8][4];
#pragma unroll
        for (int j = 0; j < 8; j++)
#pragma unroll
            for (int e = 0; e < 4; e++) s[j][e] = 0.f;
#pragma unroll
        for (int ks = 0; ks < 4; ks++) {
#pragma unroll
            for (int nb = 0; nb < 4; nb++) {
                uint32_t bh[4], bl[4];
                ldsm4(bh, pKh + 2u * ((nb * 16 + b_row) * ST2 + ks * 16 + b_k));
                ldsm4(bl, pKl + 2u * ((nb * 16 + b_row) * ST2 + ks * 16 + b_k));
#pragma unroll
                for (int hn = 0; hn < 2; hn++) {
                    int j = nb * 2 + hn;
                    mma16816(s[j], qh[ks], bh + hn * 2);
                    mma16816(s[j], qh[ks], bl + hn * 2);
                    mma16816(s[j], ql[ks], bh + hn * 2);
                }
            }
        }

        // ---- scale + causal mask (diagonal tile only) + online softmax ----
        const bool diag = (k0 + 64 >= kend);
        float mx0 = -3.0e38f, mx1 = -3.0e38f;
#pragma unroll
        for (int j = 0; j < 8; j++) {
            int colb = k0 + j * 8 + (lane & 3) * 2;
#pragma unroll
            for (int e = 0; e < 4; e++) {
                float val = s[j][e] * 0.125f;
                if (diag) {
                    int col = colb + (e & 1);
                    int qr  = (e < 2) ? qr0 : qr1;
                    if (col > qr) val = -1.0e9f;
                }
                s[j][e] = val;
                if (e < 2) mx0 = fmaxf(mx0, val); else mx1 = fmaxf(mx1, val);
            }
        }
        mx0 = fmaxf(mx0, __shfl_xor_sync(0xffffffffu, mx0, 1));
        mx0 = fmaxf(mx0, __shfl_xor_sync(0xffffffffu, mx0, 2));
        mx1 = fmaxf(mx1, __shfl_xor_sync(0xffffffffu, mx1, 1));
        mx1 = fmaxf(mx1, __shfl_xor_sync(0xffffffffu, mx1, 2));
        float nm0 = fmaxf(m0, mx0), nm1 = fmaxf(m1, mx1);
        float c0 = __expf(m0 - nm0), c1 = __expf(m1 - nm1);
        l0 *= c0; l1 *= c1;
#pragma unroll
        for (int j = 0; j < 8; j++) {
            o[j][0] *= c0; o[j][1] *= c0;
            o[j][2] *= c1; o[j][3] *= c1;
        }
        m0 = nm0; m1 = nm1;
        float rs0 = 0.f, rs1 = 0.f;
#pragma unroll
        for (int j = 0; j < 8; j++) {
#pragma unroll
            for (int e = 0; e < 4; e++) {
                float p = __expf(s[j][e] - ((e < 2) ? m0 : m1));
                s[j][e] = p;
                if (e < 2) rs0 += p; else rs1 += p;
            }
        }
        l0 += rs0; l1 += rs1;

        // ---- P fragments (hi/lo) ----
        uint32_t ph[4][4], pl_[4][4];
#pragma unroll
        for (int kg = 0; kg < 4; kg++) {
#pragma unroll
            for (int q2 = 0; q2 < 2; q2++) {        // q2=0 -> tile 2kg (elems 0,1 / 2,3)
                int j = 2 * kg + q2;
#pragma unroll
                for (int half = 0; half < 2; half++) {
                    float v0 = s[j][half * 2], v1 = s[j][half * 2 + 1];
                    float h0 = __bfloat162float(__float2bfloat16(v0));
                    float h1 = __bfloat162float(__float2bfloat16(v1));
                    ph[kg][q2 * 2 + half]  = pack_bf16(h0, h1);
                    pl_[kg][q2 * 2 + half] = pack_bf16(v0 - h0, v1 - h1);
                }
            }
        }
        // note: index mapping a0=(tile 2kg, rows r), a1=(tile 2kg, rows r+8),
        // a2/a3 same for tile 2kg+1 -> ph[kg] = {t0e01, t0e23, t1e01, t1e23}

        // ---- O += P V (bf16x3), V via ldmatrix.trans ----
#pragma unroll
        for (int kg = 0; kg < 4; kg++) {
#pragma unroll
            for (int dt = 0; dt < 4; dt++) {
                uint32_t vhf[4], vlf[4];
                uint32_t vaddr = 2u * ((kg * 16 + (lane & 15)) * ST2 + dt * 16 + (lane >> 4) * 8);
                ldsm4t(vhf, pVh + vaddr);
                ldsm4t(vlf, pVl + vaddr);
#pragma unroll
                for (int hn = 0; hn < 2; hn++) {
                    int d = dt * 2 + hn;
                    mma16816(o[d], ph[kg], vhf + hn * 2);
                    mma16816(o[d], ph[kg], vlf + hn * 2);
                    mma16816(o[d], pl_[kg], vhf + hn * 2);
                }
            }
        }
        __syncthreads();
    }

    // ---- finalize: reduce l across the 4 lanes of each row, write O ----
    l0 += __shfl_xor_sync(0xffffffffu, l0, 1);
    l0 += __shfl_xor_sync(0xffffffffu, l0, 2);
    l1 += __shfl_xor_sync(0xffffffffu, l1, 1);
    l1 += __shfl_xor_sync(0xffffffffu, l1, 2);
    float inv0 = 1.f / l0, inv1 = 1.f / l1;
    const size_t obase = ((size_t)(b * S_) + qb * 64 + w * 16) * H_ + h * HD;
#pragma unroll
    for (int j = 0; j < 8; j++) {
        int col = j * 8 + (lane & 3) * 2;
        *(float2*)&O[obase + (size_t)(lane >> 2) * H_ + col] =
            make_float2(o[j][0] * inv0, o[j][1] * inv0);
        *(float2*)&O[obase + (size_t)((lane >> 2) + 8) * H_ + col] =
            make_float2(o[j][2] * inv1, o[j][3] * inv1);
    }
}

// ---------------------------------------------------------------------------
// inputs: x, position_ids(unused), mask(unused), wq, wk, wv, wo
// ---------------------------------------------------------------------------
extern "C" void kernel_launch(void* const* d_in, const int* in_sizes, int n_in,
                              void* d_out, int out_size) {
    const float* x  = (const float*)d_in[0];
    const float* wq = (const float*)d_in[3];
    const float* wk = (const float*)d_in[4];
    const float* wv = (const float*)d_in[5];
    const float* wo = (const float*)d_in[6];
    float* out = (float*)d_out;

    float *q, *k, *v, *ao;
    cudaGetSymbolAddress((void**)&q,  g_q);
    cudaGetSymbolAddress((void**)&k,  g_k);
    cudaGetSymbolAddress((void**)&v,  g_v);
    cudaGetSymbolAddress((void**)&ao, g_ao);
    __nv_bfloat16 *qh, *ql, *kh, *kl, *vh, *vl;
    cudaGetSymbolAddress((void**)&qh, g_qh);
    cudaGetSymbolAddress((void**)&ql, g_ql);
    cudaGetSymbolAddress((void**)&kh, g_kh);
    cudaGetSymbolAddress((void**)&kl, g_kl);
    cudaGetSymbolAddress((void**)&vh, g_vh);
    cudaGetSymbolAddress((void**)&vl, g_vl);

    cs_table_kernel<<<(S_ * 32 + 255) / 256, 256>>>();

    dim3 gq(H_ / 128, MROWS / 128);
    dim3 gkv(KVD / 128, MROWS / 128);
    gemm_bf16x3<<<gq, 256>>>(x, wq, q, MROWS, H_, H_);
    gemm_bf16x3<<<gkv, 256>>>(x, wk, k, MROWS, KVD, H_);
    gemm_bf16x3<<<gkv, 256>>>(x, wv, v, MROWS, KVD, H_);

    int total = MROWS * 1024 + MROWS * 256 + MROWS * 256;
    rope_split_kernel<<<(total + 255) / 256, 256>>>(q, k, v);

    dim3 ga(S_ / 64, NH, B_);              // 32 x 32 x 2
    flash2<<<ga, 128>>>(qh, ql, kh, kl, vh, vl, ao);

    gemm_bf16x3<<<gq, 256>>>(ao, wo, out, MROWS, H_, H_);
}

// round 5
// speedup vs baseline: 4.0876x; 1.1878x over previous
#include <cuda_runtime.h>
#include <cuda_bf16.h>
#include <math.h>
#include <stdint.h>

// Problem constants
#define B_    2
#define S_    2048
#define H_    2048
#define NH    32
#define NKV   8
#define HD    64
#define KVD   512           // NKV * HD
#define MROWS 4096          // B_ * S_

// fp32 scratch
__device__ float g_q [MROWS * H_];
__device__ float g_k [MROWS * KVD];
__device__ float g_v [MROWS * KVD];
__device__ float2 g_cs[S_ * 32];

// bf16 hi/lo splits
__device__ __nv_bfloat16 g_xh [MROWS * H_],  g_xl [MROWS * H_];
__device__ __nv_bfloat16 g_wqh[H_ * H_],     g_wql[H_ * H_];
__device__ __nv_bfloat16 g_wkh[KVD * H_],    g_wkl[KVD * H_];
__device__ __nv_bfloat16 g_wvh[KVD * H_],    g_wvl[KVD * H_];
__device__ __nv_bfloat16 g_woh[H_ * H_],     g_wol[H_ * H_];
__device__ __nv_bfloat16 g_aoh[MROWS * H_],  g_aol[MROWS * H_];
__device__ __nv_bfloat16 g_qh[MROWS * H_],   g_ql[MROWS * H_];
__device__ __nv_bfloat16 g_kh[MROWS * KVD],  g_kl[MROWS * KVD];
__device__ __nv_bfloat16 g_vh[MROWS * KVD],  g_vl[MROWS * KVD];

// ---------------------------------------------------------------------------
// helpers
// ---------------------------------------------------------------------------
__device__ __forceinline__ void mma16816(float* c, const uint32_t* a, const uint32_t* b) {
    asm volatile(
        "mma.sync.aligned.m16n8k16.row.col.f32.bf16.bf16.f32 "
        "{%0,%1,%2,%3}, {%4,%5,%6,%7}, {%8,%9}, {%0,%1,%2,%3};\n"
        : "+f"(c[0]), "+f"(c[1]), "+f"(c[2]), "+f"(c[3])
        : "r"(a[0]), "r"(a[1]), "r"(a[2]), "r"(a[3]), "r"(b[0]), "r"(b[1]));
}
__device__ __forceinline__ void ldsm4(uint32_t* r, uint32_t addr) {
    asm volatile("ldmatrix.sync.aligned.m8n8.x4.shared.b16 {%0,%1,%2,%3}, [%4];\n"
                 : "=r"(r[0]), "=r"(r[1]), "=r"(r[2]), "=r"(r[3]) : "r"(addr));
}
__device__ __forceinline__ void ldsm4t(uint32_t* r, uint32_t addr) {
    asm volatile("ldmatrix.sync.aligned.m8n8.x4.trans.shared.b16 {%0,%1,%2,%3}, [%4];\n"
                 : "=r"(r[0]), "=r"(r[1]), "=r"(r[2]), "=r"(r[3]) : "r"(addr));
}
__device__ __forceinline__ uint32_t pack_bf16(float a, float b) {
    __nv_bfloat162 t = __floats2bfloat162_rn(a, b);
    return *(uint32_t*)&t;
}
__device__ __forceinline__ void cp16(uint32_t dst, const void* src) {
    asm volatile("cp.async.cg.shared.global [%0], [%1], 16;\n" :: "r"(dst), "l"(src));
}

// ---------------------------------------------------------------------------
// hi/lo split: src fp32 -> h,l bf16
// ---------------------------------------------------------------------------
__global__ void split_kernel(const float* __restrict__ src,
                             __nv_bfloat16* __restrict__ h,
                             __nv_bfloat16* __restrict__ l, int n) {
    int i = (blockIdx.x * blockDim.x + threadIdx.x) * 4;
    if (i >= n) return;
    float4 v = *(const float4*)(src + i);
    __nv_bfloat16 h0 = __float2bfloat16(v.x), h1 = __float2bfloat16(v.y);
    __nv_bfloat16 h2 = __float2bfloat16(v.z), h3 = __float2bfloat16(v.w);
    *(__nv_bfloat162*)&h[i]     = __nv_bfloat162(h0, h1);
    *(__nv_bfloat162*)&h[i + 2] = __nv_bfloat162(h2, h3);
    *(__nv_bfloat162*)&l[i] = __nv_bfloat162(
        __float2bfloat16(v.x - __bfloat162float(h0)),
        __float2bfloat16(v.y - __bfloat162float(h1)));
    *(__nv_bfloat162*)&l[i + 2] = __nv_bfloat162(
        __float2bfloat16(v.z - __bfloat162float(h2)),
        __float2bfloat16(v.w - __bfloat162float(h3)));
}

// ---------------------------------------------------------------------------
// Pipelined bf16x3 GEMM: C[M,N] = (Ah+Al)[M,K] @ (Bh+Bl)[N,K]^T
// 128x128 tile, BK=32, 3-stage cp.async pipeline, 256 threads, warp tile 64x32
// ---------------------------------------------------------------------------
#define ST 40                      // smem row stride (bf16 elems)
#define ABYTES (128 * ST * 2)      // 10240 per array
#define STAGEB (4 * ABYTES)        // 40960 per stage
#define SMEMSZ (3 * STAGEB)        // 122880

__global__ void __launch_bounds__(256)
gemm_pre(const __nv_bfloat16* __restrict__ Ah, const __nv_bfloat16* __restrict__ Al,
         const __nv_bfloat16* __restrict__ Bh, const __nv_bfloat16* __restrict__ Bl,
         float* __restrict__ C, int M, int N, int K) {
    extern __shared__ char dsm[];
    const uint32_t smem0 = (uint32_t)__cvta_generic_to_shared(dsm);

    const int t    = threadIdx.x;
    const int lane = t & 31;
    const int w    = t >> 5;
    const int wm   = (w & 1) * 64;
    const int wn   = (w >> 1) * 32;
    const int m0   = blockIdx.y * 128;
    const int n0   = blockIdx.x * 128;

    const int g = lane >> 3, r = lane & 7;
    const int a_moff = (g & 1) * 8 + r;
    const int a_koff = (g >> 1) * 8;
    const int b_noff = (g >> 1) * 8 + r;
    const int b_koff = (g & 1) * 8;

    // per-thread load coords: 2 chunks of 16B per array per stage
    const int id0 = t, id1 = t + 256;
    const int r0 = id0 >> 2, c0 = (id0 & 3) * 8;
    const int r1 = id1 >> 2, c1 = (id1 & 3) * 8;

    const int nkt = K >> 5;

    auto issue = [&](int kt) {
        int s = kt % 3;
        int k0 = kt << 5;
        uint32_t base = smem0 + s * STAGEB;
        uint32_t d0 = base + (r0 * ST + c0) * 2;
        uint32_t d1 = base + (r1 * ST + c1) * 2;
        size_t ao0 = (size_t)(m0 + r0) * K + k0 + c0;
        size_t ao1 = (size_t)(m0 + r1) * K + k0 + c1;
        size_t bo0 = (size_t)(n0 + r0) * K + k0 + c0;
        size_t bo1 = (size_t)(n0 + r1) * K + k0 + c1;
        cp16(d0,              Ah + ao0); cp16(d1,              Ah + ao1);
        cp16(d0 + ABYTES,     Al + ao0); cp16(d1 + ABYTES,     Al + ao1);
        cp16(d0 + 2 * ABYTES, Bh + bo0); cp16(d1 + 2 * ABYTES, Bh + bo1);
        cp16(d0 + 3 * ABYTES, Bl + bo0); cp16(d1 + 3 * ABYTES, Bl + bo1);
    };

    float acc[4][4][4];
#pragma unroll
    for (int i = 0; i < 4; i++)
#pragma unroll
        for (int j = 0; j < 4; j++)
#pragma unroll
            for (int e = 0; e < 4; e++) acc[i][j][e] = 0.f;

    issue(0); asm volatile("cp.async.commit_group;\n");
    issue(1); asm volatile("cp.async.commit_group;\n");

    for (int kt = 0; kt < nkt; kt++) {
        asm volatile("cp.async.wait_group 1;\n");
        __syncthreads();
        if (kt + 2 < nkt) issue(kt + 2);
        asm volatile("cp.async.commit_group;\n");

        const uint32_t base = smem0 + (kt % 3) * STAGEB;
        const uint32_t sAh = base, sAl = base + ABYTES;
        const uint32_t sBh = base + 2 * ABYTES, sBl = base + 3 * ABYTES;

#pragma unroll
        for (int ks = 0; ks < 2; ks++) {
            const int kk = ks * 16;
            uint32_t af[4][4], b1[2][4], b2[2][4];
#pragma unroll
            for (int mi = 0; mi < 4; mi++)
                ldsm4(af[mi], sAh + 2u * ((wm + mi * 16 + a_moff) * ST + kk + a_koff));
#pragma unroll
            for (int nb = 0; nb < 2; nb++) {
                ldsm4(b1[nb], sBh + 2u * ((wn + nb * 16 + b_noff) * ST + kk + b_koff));
                ldsm4(b2[nb], sBl + 2u * ((wn + nb * 16 + b_noff) * ST + kk + b_koff));
            }
#pragma unroll
            for (int mi = 0; mi < 4; mi++)
#pragma unroll
                for (int ni = 0; ni < 4; ni++) {
                    mma16816(acc[mi][ni], af[mi], &b1[ni >> 1][(ni & 1) * 2]);
                    mma16816(acc[mi][ni], af[mi], &b2[ni >> 1][(ni & 1) * 2]);
                }
#pragma unroll
            for (int mi = 0; mi < 4; mi++)
                ldsm4(af[mi], sAl + 2u * ((wm + mi * 16 + a_moff) * ST + kk + a_koff));
#pragma unroll
            for (int mi = 0; mi < 4; mi++)
#pragma unroll
                for (int ni = 0; ni < 4; ni++)
                    mma16816(acc[mi][ni], af[mi], &b1[ni >> 1][(ni & 1) * 2]);
        }
        __syncthreads();
    }

#pragma unroll
    for (int mi = 0; mi < 4; mi++) {
        int row = m0 + wm + mi * 16 + (lane >> 2);
#pragma unroll
        for (int ni = 0; ni < 4; ni++) {
            int col = n0 + wn + ni * 8 + (lane & 3) * 2;
            *(float2*)&C[(size_t)row * N + col]       = make_float2(acc[mi][ni][0], acc[mi][ni][1]);
            *(float2*)&C[(size_t)(row + 8) * N + col] = make_float2(acc[mi][ni][2], acc[mi][ni][3]);
        }
    }
}

// ---------------------------------------------------------------------------
// cos/sin table
// ---------------------------------------------------------------------------
__global__ void cs_table_kernel() {
    int i = blockIdx.x * blockDim.x + threadIdx.x;
    if (i >= S_ * 32) return;
    int pos = i >> 5, p = i & 31;
    double inv = exp(-((double)(2 * p) / 64.0) * log(10000.0));
    double ang = (double)pos * inv;
    g_cs[i] = make_float2((float)cos(ang), (float)sin(ang));
}

// ---------------------------------------------------------------------------
// Fused RoPE (Q,K) + hi/lo split of Q, K, V
// ---------------------------------------------------------------------------
__global__ void rope_split_kernel(const float* __restrict__ q,
                                  const float* __restrict__ k,
                                  const float* __restrict__ v) {
    const int NQ = MROWS * 1024;
    const int NK = MROWS * 256;
    const int NV = MROWS * 256;
    int idx = blockIdx.x * blockDim.x + threadIdx.x;
    if (idx >= NQ + NK + NV) return;

    if (idx < NQ + NK) {
        const float* src; __nv_bfloat16 *dh, *dl;
        int row, p, head, rowstride;
        if (idx < NQ) {
            row = idx >> 10; int rem = idx & 1023;
            head = rem >> 5; p = rem & 31; rowstride = H_;
            src = q; dh = g_qh; dl = g_ql;
        } else {
            int i2 = idx - NQ;
            row = i2 >> 8; int rem = i2 & 255;
            head = rem >> 5; p = rem & 31; rowstride = KVD;
            src = k; dh = g_kh; dl = g_kl;
        }
        size_t base = (size_t)row * rowstride + head * HD;
        int pos = row & (S_ - 1);
        float2 cs = g_cs[pos * 32 + p];
        float x0 = src[base + p], x1 = src[base + p + 32];
        float y0 = x0 * cs.x - x1 * cs.y;
        float y1 = x1 * cs.x + x0 * cs.y;
        __nv_bfloat16 h0 = __float2bfloat16(y0);
        __nv_bfloat16 h1 = __float2bfloat16(y1);
        dh[base + p]      = h0;
        dh[base + p + 32] = h1;
        dl[base + p]      = __float2bfloat16(y0 - __bfloat162float(h0));
        dl[base + p + 32] = __float2bfloat16(y1 - __bfloat162float(h1));
    } else {
        int i2 = idx - NQ - NK;
        size_t base = (size_t)(i2 >> 8) * KVD + (i2 & 255) * 2;
        float x0 = v[base], x1 = v[base + 1];
        __nv_bfloat16 h0 = __float2bfloat16(x0);
        __nv_bfloat16 h1 = __float2bfloat16(x1);
        g_vh[base]     = h0;
        g_vh[base + 1] = h1;
        g_vl[base]     = __float2bfloat16(x0 - __bfloat162float(h0));
        g_vl[base + 1] = __float2bfloat16(x1 - __bfloat162float(h1));
    }
}

// ---------------------------------------------------------------------------
// Tensor-core causal flash attention; epilogue writes bf16 hi/lo of output.
// ---------------------------------------------------------------------------
#define ST2 72

__global__ void __launch_bounds__(128)
flash2(const __nv_bfloat16* __restrict__ Qh, const __nv_bfloat16* __restrict__ Ql,
       const __nv_bfloat16* __restrict__ Kh, const __nv_bfloat16* __restrict__ Kl,
       const __nv_bfloat16* __restrict__ Vh, const __nv_bfloat16* __restrict__ Vl,
       __nv_bfloat16* __restrict__ AOh, __nv_bfloat16* __restrict__ AOl) {
    __shared__ __nv_bfloat16 sKh[64 * ST2], sKl[64 * ST2];
    __shared__ __nv_bfloat16 sVh[64 * ST2], sVl[64 * ST2];

    const int t = threadIdx.x, lane = t & 31, w = t >> 5;
    const int qb = blockIdx.x, h = blockIdx.y, b = blockIdx.z, kvh = h >> 2;
    const int g = lane >> 3, r = lane & 7;
    const int a_row = (g & 1) * 8 + r, a_k = (g >> 1) * 8;
    const int b_row = (g >> 1) * 8 + r, b_k = (g & 1) * 8;

    const uint32_t pKh = (uint32_t)__cvta_generic_to_shared(sKh);
    const uint32_t pKl = (uint32_t)__cvta_generic_to_shared(sKl);
    const uint32_t pVh = (uint32_t)__cvta_generic_to_shared(sVh);
    const uint32_t pVl = (uint32_t)__cvta_generic_to_shared(sVl);

    const size_t qbase = ((size_t)(b * S_) + qb * 64) * H_ + h * HD;
#pragma unroll
    for (int i = 0; i < 4; i++) {
        int idx = t + i * 128;
        int row = idx >> 3, c = (idx & 7) * 8;
        *(uint4*)&sKh[row * ST2 + c] = *(const uint4*)(Qh + qbase + (size_t)row * H_ + c);
        *(uint4*)&sKl[row * ST2 + c] = *(const uint4*)(Ql + qbase + (size_t)row * H_ + c);
    }
    __syncthreads();
    uint32_t qh[4][4], ql[4][4];
#pragma unroll
    for (int ks = 0; ks < 4; ks++) {
        ldsm4(qh[ks], pKh + 2u * ((w * 16 + a_row) * ST2 + ks * 16 + a_k));
        ldsm4(ql[ks], pKl + 2u * ((w * 16 + a_row) * ST2 + ks * 16 + a_k));
    }
    __syncthreads();

    float o[8][4];
#pragma unroll
    for (int j = 0; j < 8; j++)
#pragma unroll
        for (int e = 0; e < 4; e++) o[j][e] = 0.f;
    float m0 = -3.0e38f, m1 = -3.0e38f, l0 = 0.f, l1 = 0.f;
    const int qr0 = qb * 64 + w * 16 + (lane >> 2);
    const int qr1 = qr0 + 8;
    const int kend = qb * 64 + 64;

    for (int k0 = 0; k0 < kend; k0 += 64) {
        const size_t kb = ((size_t)(b * S_) + k0) * KVD + kvh * HD;
#pragma unroll
        for (int i = 0; i < 4; i++) {
            int idx = t + i * 128;
            int row = idx >> 3, c = (idx & 7) * 8;
            size_t go = kb + (size_t)row * KVD + c;
            int so = row * ST2 + c;
            *(uint4*)&sKh[so] = *(const uint4*)(Kh + go);
            *(uint4*)&sKl[so] = *(const uint4*)(Kl + go);
            *(uint4*)&sVh[so] = *(const uint4*)(Vh + go);
            *(uint4*)&sVl[so] = *(const uint4*)(Vl + go);
        }
        __syncthreads();

        float s[8][4];
#pragma unroll
        for (int j = 0; j < 8; j++)
#pragma unroll
            for (int e = 0; e < 4; e++) s[j][e] = 0.f;
#pragma unroll
        for (int ks = 0; ks < 4; ks++) {
#pragma unroll
            for (int nb = 0; nb < 4; nb++) {
                uint32_t bh[4], bl[4];
                ldsm4(bh, pKh + 2u * ((nb * 16 + b_row) * ST2 + ks * 16 + b_k));
                ldsm4(bl, pKl + 2u * ((nb * 16 + b_row) * ST2 + ks * 16 + b_k));
#pragma unroll
                for (int hn = 0; hn < 2; hn++) {
                    int j = nb * 2 + hn;
                    mma16816(s[j], qh[ks], bh + hn * 2);
                    mma16816(s[j], qh[ks], bl + hn * 2);
                    mma16816(s[j], ql[ks], bh + hn * 2);
                }
            }
        }

        const bool diag = (k0 + 64 >= kend);
        float mx0 = -3.0e38f, mx1 = -3.0e38f;
#pragma unroll
        for (int j = 0; j < 8; j++) {
            int colb = k0 + j * 8 + (lane & 3) * 2;
#pragma unroll
            for (int e = 0; e < 4; e++) {
                float val = s[j][e] * 0.125f;
                if (diag) {
                    int col = colb + (e & 1);
                    int qr  = (e < 2) ? qr0 : qr1;
                    if (col > qr) val = -1.0e9f;
                }
                s[j][e] = val;
                if (e < 2) mx0 = fmaxf(mx0, val); else mx1 = fmaxf(mx1, val);
            }
        }
        mx0 = fmaxf(mx0, __shfl_xor_sync(0xffffffffu, mx0, 1));
        mx0 = fmaxf(mx0, __shfl_xor_sync(0xffffffffu, mx0, 2));
        mx1 = fmaxf(mx1, __shfl_xor_sync(0xffffffffu, mx1, 1));
        mx1 = fmaxf(mx1, __shfl_xor_sync(0xffffffffu, mx1, 2));
        float nm0 = fmaxf(m0, mx0), nm1 = fmaxf(m1, mx1);
        float c0 = __expf(m0 - nm0), c1 = __expf(m1 - nm1);
        l0 *= c0; l1 *= c1;
#pragma unroll
        for (int j = 0; j < 8; j++) {
            o[j][0] *= c0; o[j][1] *= c0;
            o[j][2] *= c1; o[j][3] *= c1;
        }
        m0 = nm0; m1 = nm1;
        float rs0 = 0.f, rs1 = 0.f;
#pragma unroll
        for (int j = 0; j < 8; j++) {
#pragma unroll
            for (int e = 0; e < 4; e++) {
                float p = __expf(s[j][e] - ((e < 2) ? m0 : m1));
                s[j][e] = p;
                if (e < 2) rs0 += p; else rs1 += p;
            }
        }
        l0 += rs0; l1 += rs1;

        uint32_t ph[4][4], pl_[4][4];
#pragma unroll
        for (int kg = 0; kg < 4; kg++) {
#pragma unroll
            for (int q2 = 0; q2 < 2; q2++) {
                int j = 2 * kg + q2;
#pragma unroll
                for (int half = 0; half < 2; half++) {
                    float v0 = s[j][half * 2], v1 = s[j][half * 2 + 1];
                    float h0 = __bfloat162float(__float2bfloat16(v0));
                    float h1 = __bfloat162float(__float2bfloat16(v1));
                    ph[kg][q2 * 2 + half]  = pack_bf16(h0, h1);
                    pl_[kg][q2 * 2 + half] = pack_bf16(v0 - h0, v1 - h1);
                }
            }
        }

#pragma unroll
        for (int kg = 0; kg < 4; kg++) {
#pragma unroll
            for (int dt = 0; dt < 4; dt++) {
                uint32_t vhf[4], vlf[4];
                uint32_t vaddr = 2u * ((kg * 16 + (lane & 15)) * ST2 + dt * 16 + (lane >> 4) * 8);
                ldsm4t(vhf, pVh + vaddr);
                ldsm4t(vlf, pVl + vaddr);
#pragma unroll
                for (int hn = 0; hn < 2; hn++) {
                    int d = dt * 2 + hn;
                    mma16816(o[d], ph[kg], vhf + hn * 2);
                    mma16816(o[d], ph[kg], vlf + hn * 2);
                    mma16816(o[d], pl_[kg], vhf + hn * 2);
                }
            }
        }
        __syncthreads();
    }

    l0 += __shfl_xor_sync(0xffffffffu, l0, 1);
    l0 += __shfl_xor_sync(0xffffffffu, l0, 2);
    l1 += __shfl_xor_sync(0xffffffffu, l1, 1);
    l1 += __shfl_xor_sync(0xffffffffu, l1, 2);
    float inv0 = 1.f / l0, inv1 = 1.f / l1;
    const size_t obase = ((size_t)(b * S_) + qb * 64 + w * 16) * H_ + h * HD;
#pragma unroll
    for (int j = 0; j < 8; j++) {
        int col = j * 8 + (lane & 3) * 2;
        {
            size_t off = obase + (size_t)(lane >> 2) * H_ + col;
            float v0 = o[j][0] * inv0, v1 = o[j][1] * inv0;
            __nv_bfloat16 h0 = __float2bfloat16(v0), h1 = __float2bfloat16(v1);
            *(__nv_bfloat162*)&AOh[off] = __nv_bfloat162(h0, h1);
            *(__nv_bfloat162*)&AOl[off] = __nv_bfloat162(
                __float2bfloat16(v0 - __bfloat162float(h0)),
                __float2bfloat16(v1 - __bfloat162float(h1)));
        }
        {
            size_t off = obase + (size_t)((lane >> 2) + 8) * H_ + col;
            float v0 = o[j][2] * inv1, v1 = o[j][3] * inv1;
            __nv_bfloat16 h0 = __float2bfloat16(v0), h1 = __float2bfloat16(v1);
            *(__nv_bfloat162*)&AOh[off] = __nv_bfloat162(h0, h1);
            *(__nv_bfloat162*)&AOl[off] = __nv_bfloat162(
                __float2bfloat16(v0 - __bfloat162float(h0)),
                __float2bfloat16(v1 - __bfloat162float(h1)));
        }
    }
}

// ---------------------------------------------------------------------------
// inputs: x, position_ids(unused), mask(unused), wq, wk, wv, wo
// ---------------------------------------------------------------------------
extern "C" void kernel_launch(void* const* d_in, const int* in_sizes, int n_in,
                              void* d_out, int out_size) {
    const float* x  = (const float*)d_in[0];
    const float* wq = (const float*)d_in[3];
    const float* wk = (const float*)d_in[4];
    const float* wv = (const float*)d_in[5];
    const float* wo = (const float*)d_in[6];
    float* out = (float*)d_out;

    float *q, *k, *v;
    cudaGetSymbolAddress((void**)&q, g_q);
    cudaGetSymbolAddress((void**)&k, g_k);
    cudaGetSymbolAddress((void**)&v, g_v);
    __nv_bfloat16 *xh, *xl, *wqh, *wql, *wkh, *wkl, *wvh, *wvl, *woh, *wol;
    __nv_bfloat16 *aoh, *aol, *qh, *ql, *kh, *kl, *vh, *vl;
    cudaGetSymbolAddress((void**)&xh,  g_xh);  cudaGetSymbolAddress((void**)&xl,  g_xl);
    cudaGetSymbolAddress((void**)&wqh, g_wqh); cudaGetSymbolAddress((void**)&wql, g_wql);
    cudaGetSymbolAddress((void**)&wkh, g_wkh); cudaGetSymbolAddress((void**)&wkl, g_wkl);
    cudaGetSymbolAddress((void**)&wvh, g_wvh); cudaGetSymbolAddress((void**)&wvl, g_wvl);
    cudaGetSymbolAddress((void**)&woh, g_woh); cudaGetSymbolAddress((void**)&wol, g_wol);
    cudaGetSymbolAddress((void**)&aoh, g_aoh); cudaGetSymbolAddress((void**)&aol, g_aol);
    cudaGetSymbolAddress((void**)&qh,  g_qh);  cudaGetSymbolAddress((void**)&ql,  g_ql);
    cudaGetSymbolAddress((void**)&kh,  g_kh);  cudaGetSymbolAddress((void**)&kl,  g_kl);
    cudaGetSymbolAddress((void**)&vh,  g_vh);  cudaGetSymbolAddress((void**)&vl,  g_vl);

    cudaFuncSetAttribute(gemm_pre, cudaFuncAttributeMaxDynamicSharedMemorySize, SMEMSZ);

    cs_table_kernel<<<(S_ * 32 + 255) / 256, 256>>>();

    // hi/lo splits of x and weights
    split_kernel<<<(MROWS * H_ / 4 + 255) / 256, 256>>>(x,  xh,  xl,  MROWS * H_);
    split_kernel<<<(H_ * H_ / 4 + 255) / 256, 256>>>(wq, wqh, wql, H_ * H_);
    split_kernel<<<(KVD * H_ / 4 + 255) / 256, 256>>>(wk, wkh, wkl, KVD * H_);
    split_kernel<<<(KVD * H_ / 4 + 255) / 256, 256>>>(wv, wvh, wvl, KVD * H_);
    split_kernel<<<(H_ * H_ / 4 + 255) / 256, 256>>>(wo, woh, wol, H_ * H_);

    dim3 gq(H_ / 128, MROWS / 128);
    dim3 gkv(KVD / 128, MROWS / 128);
    gemm_pre<<<gq, 256, SMEMSZ>>>(xh, xl, wqh, wql, q, MROWS, H_, H_);
    gemm_pre<<<gkv, 256, SMEMSZ>>>(xh, xl, wkh, wkl, k, MROWS, KVD, H_);
    gemm_pre<<<gkv, 256, SMEMSZ>>>(xh, xl, wvh, wvl, v, MROWS, KVD, H_);

    int total = MROWS * 1024 + MROWS * 256 + MROWS * 256;
    rope_split_kernel<<<(total + 255) / 256, 256>>>(q, k, v);

    dim3 ga(S_ / 64, NH, B_);
    flash2<<<ga, 128>>>(qh, ql, kh, kl, vh, vl, aoh, aol);

    gemm_pre<<<gq, 256, SMEMSZ>>>(aoh, aol, woh, wol, out, MROWS, H_, H_);
}